// round 8
// baseline (speedup 1.0000x reference)
#include <cuda_runtime.h>
#include <math.h>

#define N_NODES 65536
#define N_EDGES 524288
#define N_GRAPHS 64
#define PTS 1024
#define FMAX 512

// ---------------- scratch (device globals: no allocation allowed) ----------
__device__ float g_bufA[(size_t)N_NODES * FMAX];   // xw after GEMM (C)
__device__ float g_bufB[(size_t)N_NODES * FMAX];   // layer input / final output
__device__ float g_bufC[(size_t)N_NODES * FMAX];   // aggregation accumulator (D)
__device__ float g_deg[N_NODES];
__device__ float g_dinv[N_NODES];
__device__ int   g_src[N_EDGES];
__device__ int   g_dst[N_EDGES];
__device__ float g_coef[N_EDGES];
__device__ float g_h[N_GRAPHS * 1024];
__device__ float g_h2[N_GRAPHS * 512];

// ---------------- degree / normalization -----------------------------------
__global__ void k_deg_init(float* deg) {
    int i = blockIdx.x * blockDim.x + threadIdx.x;
    if (i < N_NODES) deg[i] = 1.0f;   // self-loop
}

// edge_index is int32 (JAX x64 disabled downcasts the declared int64)
__global__ void k_deg_count(const int* __restrict__ ei, float* deg) {
    int e = blockIdx.x * blockDim.x + threadIdx.x;
    if (e < N_EDGES) {
        int c = ei[N_EDGES + e];
        if ((unsigned)c < N_NODES) atomicAdd(&deg[c], 1.0f);
    }
}

__global__ void k_dinv(const float* __restrict__ deg, float* __restrict__ dinv) {
    int i = blockIdx.x * blockDim.x + threadIdx.x;
    if (i < N_NODES) dinv[i] = 1.0f / sqrtf(deg[i]);
}

// Precompute endpoints + per-edge normalization coefficient.
__global__ void k_edge_prep(const int* __restrict__ ei,
                            const float* __restrict__ dinv,
                            int* __restrict__ src, int* __restrict__ dst,
                            float* __restrict__ coef) {
    int e = blockIdx.x * blockDim.x + threadIdx.x;
    if (e >= N_EDGES) return;
    int r = ei[e];
    int c = ei[N_EDGES + e];
    src[e] = r;
    dst[e] = c;
    coef[e] = dinv[r] * dinv[c];
}

// ---------------- layer-1 GEMM (K=3, N=64), fused self-loop init ------------
__global__ void k_gemm1(const float* __restrict__ x, const float* __restrict__ W,
                        float* __restrict__ xw, float* __restrict__ outInit,
                        const float* __restrict__ dinv) {
    __shared__ float Ws[192];
    int t = threadIdx.x;
    if (t < 192) Ws[t] = W[t];
    __syncthreads();
    int idx = blockIdx.x * blockDim.x + t;       // N_NODES*64 total
    int i = idx >> 6;
    int j = idx & 63;
    float x0 = x[i * 3 + 0], x1 = x[i * 3 + 1], x2 = x[i * 3 + 2];
    float v = x0 * Ws[j] + x1 * Ws[64 + j] + x2 * Ws[128 + j];
    xw[idx] = v;
    float d = dinv[i];
    outInit[idx] = v * d * d;
}

// ---------------- tiled SGEMM, 64x64 tile, BK=16, 4x4/thread ----------------
// C = A @ B  (A: MxK, B: KxN, row-major); D = C * dinv[row]^2 (fused self-loop)
__global__ void k_sgemm(const float* __restrict__ A, const float* __restrict__ Bm,
                        float* __restrict__ C, float* __restrict__ D,
                        const float* __restrict__ dinv, int N, int K) {
    const int BK = 16;
    __shared__ float As[BK][65];   // padded: conflict-free transposed store
    __shared__ float Bs[BK][64];
    int tid = threadIdx.x;                 // 256 threads
    int tx = tid & 15, ty = tid >> 4;
    int rowBase = blockIdx.y * 64;
    int colBase = blockIdx.x * 64;
    float acc[4][4] = {};

    for (int k0 = 0; k0 < K; k0 += BK) {
#pragma unroll
        for (int l = 0; l < 4; l++) {           // A tile: 64 rows x 16 k
            int idx = tid + l * 256;
            int r = idx >> 4;
            int k = idx & 15;
            As[k][r] = A[(size_t)(rowBase + r) * K + k0 + k];
        }
#pragma unroll
        for (int l = 0; l < 4; l++) {           // B tile: 16 k x 64 cols
            int idx = tid + l * 256;
            int k = idx >> 6;
            int c = idx & 63;
            Bs[k][c] = Bm[(size_t)(k0 + k) * N + colBase + c];
        }
        __syncthreads();
#pragma unroll
        for (int k = 0; k < BK; k++) {
            float a[4], b[4];
#pragma unroll
            for (int i = 0; i < 4; i++) a[i] = As[k][ty * 4 + i];
#pragma unroll
            for (int j = 0; j < 4; j++) b[j] = Bs[k][tx * 4 + j];
#pragma unroll
            for (int i = 0; i < 4; i++)
#pragma unroll
                for (int j = 0; j < 4; j++) acc[i][j] += a[i] * b[j];
        }
        __syncthreads();
    }
#pragma unroll
    for (int i = 0; i < 4; i++) {
        int r = rowBase + ty * 4 + i;
        float d = dinv[r];
        float d2 = d * d;
#pragma unroll
        for (int j = 0; j < 4; j++) {
            size_t o = (size_t)r * N + colBase + tx * 4 + j;
            float v = acc[i][j];
            C[o] = v;
            D[o] = v * d2;
        }
    }
}

// ---------------- edge scatter: out[dst] += xw[src] * coef ------------------
template <int F>
__global__ void k_scatter(const int* __restrict__ src, const int* __restrict__ dst,
                          const float* __restrict__ coef,
                          const float* __restrict__ xw,
                          float* __restrict__ out) {
    const int FV = F / 4;
    const int SH = (F == 64) ? 4 : (F == 256) ? 6 : 7;   // log2(FV)
    long long idx = (long long)blockIdx.x * blockDim.x + threadIdx.x;
    if (idx >= (long long)N_EDGES * FV) return;
    int e = (int)(idx >> SH);
    int f4 = ((int)idx & (FV - 1)) * 4;
    int r = src[e];
    int c = dst[e];
    float w = coef[e];
    float4 v = *(const float4*)&xw[(size_t)r * F + f4];
    float* o = &out[(size_t)c * F + f4];
    atomicAdd(o + 0, v.x * w);
    atomicAdd(o + 1, v.y * w);
    atomicAdd(o + 2, v.z * w);
    atomicAdd(o + 3, v.w * w);
}

// ---------------- dst = relu(src + b), out of place -------------------------
template <int F>
__global__ void k_bias_relu(const float* __restrict__ src, float* __restrict__ dst,
                            const float* __restrict__ b) {
    size_t idx = (size_t)blockIdx.x * blockDim.x + threadIdx.x;  // N_NODES*F
    int f = (int)(idx & (F - 1));
    float v = src[idx] + b[f];
    dst[idx] = v > 0.f ? v : 0.f;
}

// ---------------- pooling: mean + max per graph -----------------------------
__global__ void k_pool(const float* __restrict__ x3, float* __restrict__ h) {
    int g = blockIdx.x;          // 64 graphs
    int f = threadIdx.x;         // 512 features
    const float* base = x3 + (size_t)g * PTS * 512 + f;
    float s = 0.f, m = -INFINITY;
#pragma unroll 8
    for (int n = 0; n < PTS; n++) {
        float v = base[(size_t)n * 512];
        s += v;
        m = fmaxf(m, v);
    }
    h[g * 1024 + f] = s * (1.0f / PTS);
    h[g * 1024 + 512 + f] = m;
}

// ---------------- MLP1: [64,1024] @ [1024,512] + b, relu --------------------
__global__ void k_mlp1(const float* __restrict__ h, const float* __restrict__ W,
                       const float* __restrict__ b, float* __restrict__ h2) {
    __shared__ float hs[1024];
    int g = blockIdx.x;          // 64 blocks
    int c = threadIdx.x;         // 512 threads
    for (int k = c; k < 1024; k += 512) hs[k] = h[g * 1024 + k];
    __syncthreads();
    float acc = b[c];
#pragma unroll 4
    for (int k = 0; k < 1024; k++) acc += hs[k] * W[k * 512 + c];
    h2[g * 512 + c] = acc > 0.f ? acc : 0.f;
}

// ---------------- MLP2: [64,512] @ [512,10] + b -----------------------------
__global__ void k_mlp2(const float* __restrict__ h2, const float* __restrict__ W,
                       const float* __restrict__ b, float* __restrict__ out) {
    int idx = blockIdx.x * blockDim.x + threadIdx.x;   // 640
    if (idx >= N_GRAPHS * 10) return;
    int g = idx / 10;
    int c = idx % 10;
    float acc = b[c];
    const float* hr = h2 + g * 512;
#pragma unroll 8
    for (int k = 0; k < 512; k++) acc += hr[k] * W[k * 10 + c];
    out[idx] = acc;
}

// ---------------- host orchestration ----------------------------------------
extern "C" void kernel_launch(void* const* d_in, const int* in_sizes, int n_in,
                              void* d_out, int out_size) {
    const float* x   = (const float*)d_in[0];
    const int*   ei  = (const int*)d_in[1];   // int32! JAX x64-disabled downcast
    // d_in[2] = batch (contiguous arange // 1024, not needed)
    const float* W1  = (const float*)d_in[3];
    const float* b1  = (const float*)d_in[4];
    const float* W2  = (const float*)d_in[5];
    const float* b2  = (const float*)d_in[6];
    const float* W3  = (const float*)d_in[7];
    const float* b3  = (const float*)d_in[8];
    const float* Wm1 = (const float*)d_in[9];
    const float* bm1 = (const float*)d_in[10];
    const float* Wm2 = (const float*)d_in[11];
    const float* bm2 = (const float*)d_in[12];
    float* out = (float*)d_out;

    float *bufA, *bufB, *bufC, *deg, *dinv, *coef, *h, *h2;
    int *src, *dst;
    cudaGetSymbolAddress((void**)&bufA, g_bufA);
    cudaGetSymbolAddress((void**)&bufB, g_bufB);
    cudaGetSymbolAddress((void**)&bufC, g_bufC);
    cudaGetSymbolAddress((void**)&deg,  g_deg);
    cudaGetSymbolAddress((void**)&dinv, g_dinv);
    cudaGetSymbolAddress((void**)&src,  g_src);
    cudaGetSymbolAddress((void**)&dst,  g_dst);
    cudaGetSymbolAddress((void**)&coef, g_coef);
    cudaGetSymbolAddress((void**)&h,    g_h);
    cudaGetSymbolAddress((void**)&h2,   g_h2);

    // degree + normalization + edge prep (shared by all three convs)
    k_deg_init<<<N_NODES / 256, 256>>>(deg);
    k_deg_count<<<N_EDGES / 256, 256>>>(ei, deg);
    k_dinv<<<N_NODES / 256, 256>>>(deg, dinv);
    k_edge_prep<<<N_EDGES / 256, 256>>>(ei, dinv, src, dst, coef);

    // ---- layer 1 (3 -> 64): xw->bufA, self-init->bufC, agg into bufC, relu->bufB
    k_gemm1<<<(N_NODES * 64) / 256, 256>>>(x, W1, bufA, bufC, dinv);
    k_scatter<64><<<(int)(((long long)N_EDGES * 16 + 255) / 256), 256>>>(src, dst, coef, bufA, bufC);
    k_bias_relu<64><<<(N_NODES * 64) / 256, 256>>>(bufC, bufB, b1);

    // ---- layer 2 (64 -> 256)
    {
        dim3 grid(256 / 64, N_NODES / 64);
        k_sgemm<<<grid, 256>>>(bufB, W2, bufA, bufC, dinv, 256, 64);
    }
    k_scatter<256><<<(int)(((long long)N_EDGES * 64 + 255) / 256), 256>>>(src, dst, coef, bufA, bufC);
    k_bias_relu<256><<<(N_NODES * 256) / 256, 256>>>(bufC, bufB, b2);

    // ---- layer 3 (256 -> 512)
    {
        dim3 grid(512 / 64, N_NODES / 64);
        k_sgemm<<<grid, 256>>>(bufB, W3, bufA, bufC, dinv, 512, 256);
    }
    k_scatter<512><<<(int)(((long long)N_EDGES * 128 + 255) / 256), 256>>>(src, dst, coef, bufA, bufC);
    k_bias_relu<512><<<(N_NODES * 512) / 256, 256>>>(bufC, bufB, b3);

    // ---- pooling + MLP head
    k_pool<<<N_GRAPHS, 512>>>(bufB, h);
    k_mlp1<<<N_GRAPHS, 512>>>(h, Wm1, bm1, h2);
    k_mlp2<<<(N_GRAPHS * 10 + 255) / 256, 256>>>(h2, Wm2, bm2, out);

    (void)in_sizes; (void)n_in; (void)out_size;
}

// round 9
// speedup vs baseline: 1.6877x; 1.6877x over previous
#include <cuda_runtime.h>
#include <math.h>

#define N_NODES 65536
#define N_EDGES 524288
#define N_GRAPHS 64
#define PTS 1024
#define FMAX 512

// ---------------- scratch (device globals: no allocation allowed) ----------
__device__ float g_bufA[(size_t)N_NODES * FMAX];
__device__ float g_bufB[(size_t)N_NODES * FMAX];
__device__ float g_bufC[(size_t)N_NODES * FMAX];
__device__ float g_deg[N_NODES];
__device__ float g_dinv[N_NODES];
__device__ int   g_src[N_EDGES];
__device__ int   g_dst[N_EDGES];
__device__ float g_coef[N_EDGES];
__device__ float g_h[N_GRAPHS * 1024];
__device__ float g_h2[N_GRAPHS * 512];

__global__ void k_deg_init(float* deg) {
    int i = blockIdx.x * blockDim.x + threadIdx.x;
    if (i < N_NODES) deg[i] = 1.0f;
}

__global__ void k_deg_count(const int* __restrict__ ei, float* deg) {
    int e = blockIdx.x * blockDim.x + threadIdx.x;
    if (e < N_EDGES) atomicAdd(&deg[ei[N_EDGES + e]], 1.0f);
}

__global__ void k_dinv(const float* __restrict__ deg, float* __restrict__ dinv) {
    int i = blockIdx.x * blockDim.x + threadIdx.x;
    if (i < N_NODES) dinv[i] = 1.0f / sqrtf(deg[i]);
}

__global__ void k_edge_prep(const int* __restrict__ ei,
                            const float* __restrict__ dinv,
                            int* __restrict__ src, int* __restrict__ dst,
                            float* __restrict__ coef) {
    int e = blockIdx.x * blockDim.x + threadIdx.x;
    if (e >= N_EDGES) return;
    int r = ei[e];
    int c = ei[N_EDGES + e];
    src[e] = r;
    dst[e] = c;
    coef[e] = dinv[r] * dinv[c];
}

// ---------------- layer-0 aggregation (F=3): y0 = A_hat @ x -----------------
__global__ void k_agg0_init(const float* __restrict__ x, const float* __restrict__ dinv,
                            float* __restrict__ y0) {
    int i = blockIdx.x * blockDim.x + threadIdx.x;
    if (i >= N_NODES) return;
    float d = dinv[i];
    float d2 = d * d;
    y0[i * 3 + 0] = x[i * 3 + 0] * d2;
    y0[i * 3 + 1] = x[i * 3 + 1] * d2;
    y0[i * 3 + 2] = x[i * 3 + 2] * d2;
}

__global__ void k_agg0_scatter(const int* __restrict__ src, const int* __restrict__ dst,
                               const float* __restrict__ coef,
                               const float* __restrict__ x, float* __restrict__ y0) {
    int e = blockIdx.x * blockDim.x + threadIdx.x;
    if (e >= N_EDGES) return;
    int r = src[e], c = dst[e];
    float w = coef[e];
    atomicAdd(&y0[c * 3 + 0], x[r * 3 + 0] * w);
    atomicAdd(&y0[c * 3 + 1], x[r * 3 + 1] * w);
    atomicAdd(&y0[c * 3 + 2], x[r * 3 + 2] * w);
}

// ---------------- layer-1 GEMM (K=3, N=64): x1 = relu(y0 @ W1 + b1) ---------
__global__ void k_gemm1(const float* __restrict__ y0, const float* __restrict__ W,
                        const float* __restrict__ bias,
                        float* __restrict__ x1, float* __restrict__ init,
                        const float* __restrict__ dinv) {
    __shared__ float Ws[192];
    __shared__ float bs[64];
    int t = threadIdx.x;
    if (t < 192) Ws[t] = W[t];
    if (t < 64) bs[t] = bias[t];
    __syncthreads();
    int idx = blockIdx.x * blockDim.x + t;
    int i = idx >> 6;
    int j = idx & 63;
    float a0 = y0[i * 3 + 0], a1 = y0[i * 3 + 1], a2 = y0[i * 3 + 2];
    float v = a0 * Ws[j] + a1 * Ws[64 + j] + a2 * Ws[128 + j] + bs[j];
    v = v > 0.f ? v : 0.f;
    x1[idx] = v;
    float d = dinv[i];
    init[idx] = v * d * d;
}

// ---------------- tiled SGEMM: C = relu(A@B + bias); D = C*dinv^2 (opt) -----
__global__ void k_sgemm(const float* __restrict__ A, const float* __restrict__ Bm,
                        const float* __restrict__ bias,
                        float* __restrict__ C, float* __restrict__ D,
                        const float* __restrict__ dinv, int N, int K) {
    const int BK = 16;
    __shared__ float As[BK][65];
    __shared__ float Bs[BK][64];
    int tid = threadIdx.x;
    int tx = tid & 15, ty = tid >> 4;
    int rowBase = blockIdx.y * 64;
    int colBase = blockIdx.x * 64;
    float acc[4][4] = {};

    for (int k0 = 0; k0 < K; k0 += BK) {
#pragma unroll
        for (int l = 0; l < 4; l++) {
            int idx = tid + l * 256;
            int r = idx >> 4;
            int k = idx & 15;
            As[k][r] = A[(size_t)(rowBase + r) * K + k0 + k];
        }
#pragma unroll
        for (int l = 0; l < 4; l++) {
            int idx = tid + l * 256;
            int k = idx >> 6;
            int c = idx & 63;
            Bs[k][c] = Bm[(size_t)(k0 + k) * N + colBase + c];
        }
        __syncthreads();
#pragma unroll
        for (int k = 0; k < BK; k++) {
            float a[4], b[4];
#pragma unroll
            for (int i = 0; i < 4; i++) a[i] = As[k][ty * 4 + i];
#pragma unroll
            for (int j = 0; j < 4; j++) b[j] = Bs[k][tx * 4 + j];
#pragma unroll
            for (int i = 0; i < 4; i++)
#pragma unroll
                for (int j = 0; j < 4; j++) acc[i][j] += a[i] * b[j];
        }
        __syncthreads();
    }
    float bb[4];
#pragma unroll
    for (int j = 0; j < 4; j++) bb[j] = bias[colBase + tx * 4 + j];
#pragma unroll
    for (int i = 0; i < 4; i++) {
        int r = rowBase + ty * 4 + i;
        float d = dinv[r];
        float d2 = d * d;
#pragma unroll
        for (int j = 0; j < 4; j++) {
            size_t o = (size_t)r * N + colBase + tx * 4 + j;
            float v = acc[i][j] + bb[j];
            v = v > 0.f ? v : 0.f;
            C[o] = v;
            if (D) D[o] = v * d2;
        }
    }
}

// ---------------- edge scatter: out[dst] += xw[src] * coef ------------------
template <int F>
__global__ void k_scatter(const int* __restrict__ src, const int* __restrict__ dst,
                          const float* __restrict__ coef,
                          const float* __restrict__ xw,
                          float* __restrict__ out) {
    const int FV = F / 4;
    const int SH = (F == 64) ? 4 : 6;
    long long idx = (long long)blockIdx.x * blockDim.x + threadIdx.x;
    if (idx >= (long long)N_EDGES * FV) return;
    int e = (int)(idx >> SH);
    int f4 = ((int)idx & (FV - 1)) * 4;
    int r = src[e];
    int c = dst[e];
    float w = coef[e];
    float4 v = *(const float4*)&xw[(size_t)r * F + f4];
    float* o = &out[(size_t)c * F + f4];
    atomicAdd(o + 0, v.x * w);
    atomicAdd(o + 1, v.y * w);
    atomicAdd(o + 2, v.z * w);
    atomicAdd(o + 3, v.w * w);
}

__global__ void k_pool(const float* __restrict__ x3, float* __restrict__ h) {
    int g = blockIdx.x;
    int f = threadIdx.x;
    const float* base = x3 + (size_t)g * PTS * 512 + f;
    float s = 0.f, m = -INFINITY;
#pragma unroll 8
    for (int n = 0; n < PTS; n++) {
        float v = base[(size_t)n * 512];
        s += v;
        m = fmaxf(m, v);
    }
    h[g * 1024 + f] = s * (1.0f / PTS);
    h[g * 1024 + 512 + f] = m;
}

__global__ void k_mlp1(const float* __restrict__ h, const float* __restrict__ W,
                       const float* __restrict__ b, float* __restrict__ h2) {
    __shared__ float hs[1024];
    int g = blockIdx.x;
    int c = threadIdx.x;
    for (int k = c; k < 1024; k += 512) hs[k] = h[g * 1024 + k];
    __syncthreads();
    float acc = b[c];
#pragma unroll 4
    for (int k = 0; k < 1024; k++) acc += hs[k] * W[k * 512 + c];
    h2[g * 512 + c] = acc > 0.f ? acc : 0.f;
}

__global__ void k_mlp2(const float* __restrict__ h2, const float* __restrict__ W,
                       const float* __restrict__ b, float* __restrict__ out) {
    int idx = blockIdx.x * blockDim.x + threadIdx.x;
    if (idx >= N_GRAPHS * 10) return;
    int g = idx / 10;
    int c = idx % 10;
    float acc = b[c];
    const float* hr = h2 + g * 512;
#pragma unroll 8
    for (int k = 0; k < 512; k++) acc += hr[k] * W[k * 10 + c];
    out[idx] = acc;
}

extern "C" void kernel_launch(void* const* d_in, const int* in_sizes, int n_in,
                              void* d_out, int out_size) {
    const float* x   = (const float*)d_in[0];
    const int*   ei  = (const int*)d_in[1];   // int32 (JAX x64-disabled)
    const float* W1  = (const float*)d_in[3];
    const float* b1  = (const float*)d_in[4];
    const float* W2  = (const float*)d_in[5];
    const float* b2  = (const float*)d_in[6];
    const float* W3  = (const float*)d_in[7];
    const float* b3  = (const float*)d_in[8];
    const float* Wm1 = (const float*)d_in[9];
    const float* bm1 = (const float*)d_in[10];
    const float* Wm2 = (const float*)d_in[11];
    const float* bm2 = (const float*)d_in[12];
    float* out = (float*)d_out;

    float *bufA, *bufB, *bufC, *deg, *dinv, *coef, *h, *h2;
    int *src, *dst;
    cudaGetSymbolAddress((void**)&bufA, g_bufA);
    cudaGetSymbolAddress((void**)&bufB, g_bufB);
    cudaGetSymbolAddress((void**)&bufC, g_bufC);
    cudaGetSymbolAddress((void**)&deg,  g_deg);
    cudaGetSymbolAddress((void**)&dinv, g_dinv);
    cudaGetSymbolAddress((void**)&src,  g_src);
    cudaGetSymbolAddress((void**)&dst,  g_dst);
    cudaGetSymbolAddress((void**)&coef, g_coef);
    cudaGetSymbolAddress((void**)&h,    g_h);
    cudaGetSymbolAddress((void**)&h2,   g_h2);

    k_deg_init<<<N_NODES / 256, 256>>>(deg);
    k_deg_count<<<N_EDGES / 256, 256>>>(ei, deg);
    k_dinv<<<N_NODES / 256, 256>>>(deg, dinv);
    k_edge_prep<<<N_EDGES / 256, 256>>>(ei, dinv, src, dst, coef);

    // ---- layer 1: aggregate first over F=3 (y0 -> bufB), then GEMM 3->64 ----
    k_agg0_init<<<N_NODES / 256, 256>>>(x, dinv, bufB);
    k_agg0_scatter<<<N_EDGES / 256, 256>>>(src, dst, coef, x, bufB);
    // x1 = relu(y0@W1+b1) -> bufA ; agg1 seed = x1*d^2 -> bufC
    k_gemm1<<<(N_NODES * 64) / 256, 256>>>(bufB, W1, b1, bufA, bufC, dinv);

    // ---- layer 2: aggregate over F=64 into bufC, then GEMM 64->256 ----
    k_scatter<64><<<(int)(((long long)N_EDGES * 16 + 255) / 256), 256>>>(src, dst, coef, bufA, bufC);
    {
        dim3 grid(256 / 64, N_NODES / 64);
        // x2 = relu(y1@W2+b2) -> bufA ; agg2 seed = x2*d^2 -> bufB
        k_sgemm<<<grid, 256>>>(bufC, W2, b2, bufA, bufB, dinv, 256, 64);
    }

    // ---- layer 3: aggregate over F=256 into bufB, then GEMM 256->512 ----
    k_scatter<256><<<(int)(((long long)N_EDGES * 64 + 255) / 256), 256>>>(src, dst, coef, bufA, bufB);
    {
        dim3 grid(512 / 64, N_NODES / 64);
        // x3 = relu(y2@W3+b3) -> bufC ; no next aggregation
        k_sgemm<<<grid, 256>>>(bufB, W3, b3, bufC, nullptr, dinv, 512, 256);
    }

    k_pool<<<N_GRAPHS, 512>>>(bufC, h);
    k_mlp1<<<N_GRAPHS, 512>>>(h, Wm1, bm1, h2);
    k_mlp2<<<(N_GRAPHS * 10 + 255) / 256, 256>>>(h2, Wm2, bm2, out);

    (void)in_sizes; (void)n_in; (void)out_size;
}

// round 12
// speedup vs baseline: 2.7689x; 1.6407x over previous
#include <cuda_runtime.h>
#include <math.h>

#define N_NODES 65536
#define N_EDGES 524288
#define N_GRAPHS 64
#define PTS 1024
#define FMAX 512

// ---------------- scratch (device globals: no allocation allowed) ----------
__device__ float g_bufA[(size_t)N_NODES * FMAX];
__device__ float g_bufB[(size_t)N_NODES * FMAX];
__device__ float g_bufC[(size_t)N_NODES * FMAX];
__device__ float g_dinv[N_NODES];
__device__ int   g_cnt[N_NODES];        // in-degree counts
__device__ int   g_cursor[N_NODES];     // fill cursors
__device__ int   g_tmp[N_NODES];        // scan workspace (per-block inclusive)
__device__ int   g_bsum[64];
__device__ int   g_boff[64];
__device__ int   g_rowptr[N_NODES + 1];
__device__ int   g_csrc[N_EDGES];       // CSR: source node per slot
__device__ float g_ccoef[N_EDGES];      // CSR: edge coefficient per slot
__device__ float g_h[N_GRAPHS * 1024];
__device__ float g_h2[N_GRAPHS * 512];

// ---------------- counters / normalization ---------------------------------
__global__ void k_zero2(int* cnt, int* cursor) {
    int i = blockIdx.x * blockDim.x + threadIdx.x;
    if (i < N_NODES) { cnt[i] = 0; cursor[i] = 0; }
}

// edge_index is int32 (JAX x64 disabled downcasts the declared int64)
__global__ void k_count(const int* __restrict__ ei, int* __restrict__ cnt) {
    int e = blockIdx.x * blockDim.x + threadIdx.x;
    if (e < N_EDGES) atomicAdd(&cnt[ei[N_EDGES + e]], 1);
}

__global__ void k_dinv(const int* __restrict__ cnt, float* __restrict__ dinv) {
    int i = blockIdx.x * blockDim.x + threadIdx.x;
    if (i < N_NODES) dinv[i] = rsqrtf((float)(cnt[i] + 1));   // +1 self-loop
}

// ---------------- exclusive scan of cnt -> rowptr (3 kernels) ---------------
__global__ void k_scan1(const int* __restrict__ cnt, int* __restrict__ tmp,
                        int* __restrict__ bsum) {
    __shared__ int s[1024];
    int t = threadIdx.x;
    int i = blockIdx.x * 1024 + t;
    int v = cnt[i];
    s[t] = v;
    __syncthreads();
    for (int off = 1; off < 1024; off <<= 1) {
        int x = (t >= off) ? s[t - off] : 0;
        __syncthreads();
        s[t] += x;
        __syncthreads();
    }
    tmp[i] = s[t];
    if (t == 1023) bsum[blockIdx.x] = s[t];
}

__global__ void k_scan2(const int* __restrict__ bsum, int* __restrict__ boff) {
    __shared__ int s[64];
    int t = threadIdx.x;   // 64 threads
    s[t] = bsum[t];
    __syncthreads();
    for (int off = 1; off < 64; off <<= 1) {
        int x = (t >= off) ? s[t - off] : 0;
        __syncthreads();
        s[t] += x;
        __syncthreads();
    }
    boff[t] = (t == 0) ? 0 : s[t - 1];    // exclusive
}

__global__ void k_scan3(const int* __restrict__ tmp, const int* __restrict__ boff,
                        int* __restrict__ rowptr) {
    int i = blockIdx.x * blockDim.x + threadIdx.x;
    if (i < N_NODES) {
        rowptr[i + 1] = tmp[i] + boff[i >> 10];
        if (i == 0) rowptr[0] = 0;
    }
}

// ---------------- CSR fill: slot per (dst, edge) + coefficient --------------
__global__ void k_fill(const int* __restrict__ ei, const float* __restrict__ dinv,
                       const int* __restrict__ rowptr, int* __restrict__ cursor,
                       int* __restrict__ csrc, float* __restrict__ ccoef) {
    int e = blockIdx.x * blockDim.x + threadIdx.x;
    if (e >= N_EDGES) return;
    int r = ei[e];
    int c = ei[N_EDGES + e];
    int slot = rowptr[c] + atomicAdd(&cursor[c], 1);
    csrc[slot] = r;
    ccoef[slot] = dinv[r] * dinv[c];
}

// ---------------- CSR aggregation, F=3 (one thread per node) ----------------
__global__ void k_agg3(const int* __restrict__ rowptr, const int* __restrict__ csrc,
                       const float* __restrict__ ccoef, const float* __restrict__ x,
                       const float* __restrict__ dinv, float* __restrict__ y) {
    int i = blockIdx.x * blockDim.x + threadIdx.x;
    if (i >= N_NODES) return;
    float d = dinv[i];
    float d2 = d * d;
    float a0 = x[i * 3 + 0] * d2, a1 = x[i * 3 + 1] * d2, a2 = x[i * 3 + 2] * d2;
    int beg = rowptr[i], end = rowptr[i + 1];
    for (int j = beg; j < end; j++) {
        int s = csrc[j];
        float w = ccoef[j];
        a0 += x[s * 3 + 0] * w;
        a1 += x[s * 3 + 1] * w;
        a2 += x[s * 3 + 2] * w;
    }
    y[i * 3 + 0] = a0;
    y[i * 3 + 1] = a1;
    y[i * 3 + 2] = a2;
}

// ---------------- CSR aggregation, F=64 (one warp per node, float2/lane) ----
__global__ void k_agg64(const int* __restrict__ rowptr, const int* __restrict__ csrc,
                        const float* __restrict__ ccoef, const float* __restrict__ xw,
                        const float* __restrict__ dinv, float* __restrict__ out) {
    int w = (blockIdx.x * blockDim.x + threadIdx.x) >> 5;
    int lane = threadIdx.x & 31;
    if (w >= N_NODES) return;
    float d = dinv[w];
    float d2 = d * d;
    float2 a = ((const float2*)&xw[(size_t)w * 64])[lane];
    a.x *= d2; a.y *= d2;
    int beg = rowptr[w], end = rowptr[w + 1];
    for (int j = beg; j < end; j++) {
        int s = csrc[j];
        float c = ccoef[j];
        float2 v = ((const float2*)&xw[(size_t)s * 64])[lane];
        a.x += v.x * c;
        a.y += v.y * c;
    }
    ((float2*)&out[(size_t)w * 64])[lane] = a;
}

// ---------------- CSR aggregation, F=256 (one warp per node, 2xfloat4) ------
__global__ void k_agg256(const int* __restrict__ rowptr, const int* __restrict__ csrc,
                         const float* __restrict__ ccoef, const float* __restrict__ xw,
                         const float* __restrict__ dinv, float* __restrict__ out) {
    int w = (blockIdx.x * blockDim.x + threadIdx.x) >> 5;
    int lane = threadIdx.x & 31;
    if (w >= N_NODES) return;
    float d = dinv[w];
    float d2 = d * d;
    const float4* selfrow = (const float4*)&xw[(size_t)w * 256];
    float4 a0 = selfrow[lane];        // features [lane*4, lane*4+4)
    float4 a1 = selfrow[lane + 32];   // features [128+lane*4, ...)
    a0.x *= d2; a0.y *= d2; a0.z *= d2; a0.w *= d2;
    a1.x *= d2; a1.y *= d2; a1.z *= d2; a1.w *= d2;
    int beg = rowptr[w], end = rowptr[w + 1];
    for (int j = beg; j < end; j++) {
        int s = csrc[j];
        float c = ccoef[j];
        const float4* row = (const float4*)&xw[(size_t)s * 256];
        float4 v0 = row[lane];
        float4 v1 = row[lane + 32];
        a0.x += v0.x * c; a0.y += v0.y * c; a0.z += v0.z * c; a0.w += v0.w * c;
        a1.x += v1.x * c; a1.y += v1.y * c; a1.z += v1.z * c; a1.w += v1.w * c;
    }
    float4* o = (float4*)&out[(size_t)w * 256];
    o[lane] = a0;
    o[lane + 32] = a1;
}

// ---------------- layer-1 GEMM (K=3, N=64): x1 = relu(y0 @ W1 + b1) ---------
__global__ void k_gemm1(const float* __restrict__ y0, const float* __restrict__ W,
                        const float* __restrict__ bias, float* __restrict__ x1) {
    __shared__ float Ws[192];
    __shared__ float bs[64];
    int t = threadIdx.x;
    if (t < 192) Ws[t] = W[t];
    if (t < 64) bs[t] = bias[t];
    __syncthreads();
    int idx = blockIdx.x * blockDim.x + t;
    int i = idx >> 6;
    int j = idx & 63;
    float a0 = y0[i * 3 + 0], a1 = y0[i * 3 + 1], a2 = y0[i * 3 + 2];
    float v = a0 * Ws[j] + a1 * Ws[64 + j] + a2 * Ws[128 + j] + bs[j];
    x1[idx] = v > 0.f ? v : 0.f;
}

// ---------------- 128x64-tile SGEMM: C = relu(A@B + bias) -------------------
// A: MxK row-major, B: KxN row-major. 256 threads, 8x4 outputs/thread, BK=16.
__global__ void k_sgemm128(const float* __restrict__ A, const float* __restrict__ Bm,
                           const float* __restrict__ bias, float* __restrict__ C,
                           int N, int K) {
    const int BK = 16;
    __shared__ float As[BK][133];                 // padded transposed A tile
    __shared__ __align__(16) float Bs[BK][64];
    int tid = threadIdx.x;
    int tx = tid & 15, ty = tid >> 4;
    int rowBase = blockIdx.y * 128;
    int colBase = blockIdx.x * 64;
    int ar = tid >> 2;                 // 0..63
    int ak = (tid & 3) * 4;            // 0,4,8,12
    int bk = tid >> 4;                 // 0..15
    int bc = (tid & 15) * 4;           // 0..60
    float acc[8][4] = {};

    for (int k0 = 0; k0 < K; k0 += BK) {
        float4 a0 = *(const float4*)&A[(size_t)(rowBase + ar) * K + k0 + ak];
        float4 a1 = *(const float4*)&A[(size_t)(rowBase + ar + 64) * K + k0 + ak];
        As[ak + 0][ar] = a0.x; As[ak + 1][ar] = a0.y;
        As[ak + 2][ar] = a0.z; As[ak + 3][ar] = a0.w;
        As[ak + 0][ar + 64] = a1.x; As[ak + 1][ar + 64] = a1.y;
        As[ak + 2][ar + 64] = a1.z; As[ak + 3][ar + 64] = a1.w;
        float4 b = *(const float4*)&Bm[(size_t)(k0 + bk) * N + colBase + bc];
        *(float4*)&Bs[bk][bc] = b;
        __syncthreads();
#pragma unroll
        for (int k = 0; k < BK; k++) {
            float a[8], b4[4];
#pragma unroll
            for (int i = 0; i < 8; i++) a[i] = As[k][ty * 8 + i];
#pragma unroll
            for (int j = 0; j < 4; j++) b4[j] = Bs[k][tx * 4 + j];
#pragma unroll
            for (int i = 0; i < 8; i++)
#pragma unroll
                for (int j = 0; j < 4; j++) acc[i][j] += a[i] * b4[j];
        }
        __syncthreads();
    }
    float bb[4];
#pragma unroll
    for (int j = 0; j < 4; j++) bb[j] = bias[colBase + tx * 4 + j];
#pragma unroll
    for (int i = 0; i < 8; i++) {
        int r = rowBase + ty * 8 + i;
        float4 v;
        v.x = acc[i][0] + bb[0]; v.y = acc[i][1] + bb[1];
        v.z = acc[i][2] + bb[2]; v.w = acc[i][3] + bb[3];
        v.x = v.x > 0.f ? v.x : 0.f;
        v.y = v.y > 0.f ? v.y : 0.f;
        v.z = v.z > 0.f ? v.z : 0.f;
        v.w = v.w > 0.f ? v.w : 0.f;
        *(float4*)&C[(size_t)r * N + colBase + tx * 4] = v;
    }
}

// ---------------- pooling: mean + max per graph -----------------------------
__global__ void k_pool(const float* __restrict__ x3, float* __restrict__ h) {
    int g = blockIdx.x;
    int f = threadIdx.x;
    const float* base = x3 + (size_t)g * PTS * 512 + f;
    float s = 0.f, m = -INFINITY;
#pragma unroll 8
    for (int n = 0; n < PTS; n++) {
        float v = base[(size_t)n * 512];
        s += v;
        m = fmaxf(m, v);
    }
    h[g * 1024 + f] = s * (1.0f / PTS);
    h[g * 1024 + 512 + f] = m;
}

__global__ void k_mlp1(const float* __restrict__ h, const float* __restrict__ W,
                       const float* __restrict__ b, float* __restrict__ h2) {
    __shared__ float hs[1024];
    int g = blockIdx.x;
    int c = threadIdx.x;
    for (int k = c; k < 1024; k += 512) hs[k] = h[g * 1024 + k];
    __syncthreads();
    float acc = b[c];
#pragma unroll 4
    for (int k = 0; k < 1024; k++) acc += hs[k] * W[k * 512 + c];
    h2[g * 512 + c] = acc > 0.f ? acc : 0.f;
}

__global__ void k_mlp2(const float* __restrict__ h2, const float* __restrict__ W,
                       const float* __restrict__ b, float* __restrict__ out) {
    int idx = blockIdx.x * blockDim.x + threadIdx.x;
    if (idx >= N_GRAPHS * 10) return;
    int g = idx / 10;
    int c = idx % 10;
    float acc = b[c];
    const float* hr = h2 + g * 512;
#pragma unroll 8
    for (int k = 0; k < 512; k++) acc += hr[k] * W[k * 10 + c];
    out[idx] = acc;
}

// ---------------- host orchestration ----------------------------------------
extern "C" void kernel_launch(void* const* d_in, const int* in_sizes, int n_in,
                              void* d_out, int out_size) {
    const float* x   = (const float*)d_in[0];
    const int*   ei  = (const int*)d_in[1];   // int32 (JAX x64-disabled)
    const float* W1  = (const float*)d_in[3];
    const float* b1  = (const float*)d_in[4];
    const float* W2  = (const float*)d_in[5];
    const float* b2  = (const float*)d_in[6];
    const float* W3  = (const float*)d_in[7];
    const float* b3  = (const float*)d_in[8];
    const float* Wm1 = (const float*)d_in[9];
    const float* bm1 = (const float*)d_in[10];
    const float* Wm2 = (const float*)d_in[11];
    const float* bm2 = (const float*)d_in[12];
    float* out = (float*)d_out;

    float *bufA, *bufB, *bufC, *dinv, *ccoef, *h, *h2;
    int *cnt, *cursor, *tmp, *bsum, *boff, *rowptr, *csrc;
    cudaGetSymbolAddress((void**)&bufA,   g_bufA);
    cudaGetSymbolAddress((void**)&bufB,   g_bufB);
    cudaGetSymbolAddress((void**)&bufC,   g_bufC);
    cudaGetSymbolAddress((void**)&dinv,   g_dinv);
    cudaGetSymbolAddress((void**)&cnt,    g_cnt);
    cudaGetSymbolAddress((void**)&cursor, g_cursor);
    cudaGetSymbolAddress((void**)&tmp,    g_tmp);
    cudaGetSymbolAddress((void**)&bsum,   g_bsum);
    cudaGetSymbolAddress((void**)&boff,   g_boff);
    cudaGetSymbolAddress((void**)&rowptr, g_rowptr);
    cudaGetSymbolAddress((void**)&csrc,   g_csrc);
    cudaGetSymbolAddress((void**)&ccoef,  g_ccoef);
    cudaGetSymbolAddress((void**)&h,      g_h);
    cudaGetSymbolAddress((void**)&h2,     g_h2);

    // ---- CSR build (by destination) + normalization ----
    k_zero2<<<N_NODES / 256, 256>>>(cnt, cursor);
    k_count<<<N_EDGES / 256, 256>>>(ei, cnt);
    k_dinv<<<N_NODES / 256, 256>>>(cnt, dinv);
    k_scan1<<<64, 1024>>>(cnt, tmp, bsum);
    k_scan2<<<1, 64>>>(bsum, boff);
    k_scan3<<<N_NODES / 256, 256>>>(tmp, boff, rowptr);
    k_fill<<<N_EDGES / 256, 256>>>(ei, dinv, rowptr, cursor, csrc, ccoef);

    // ---- layer 1: aggregate F=3 (y0 -> bufB), GEMM 3->64 (x1 -> bufA) ----
    k_agg3<<<N_NODES / 256, 256>>>(rowptr, csrc, ccoef, x, dinv, bufB);
    k_gemm1<<<(N_NODES * 64) / 256, 256>>>(bufB, W1, b1, bufA);

    // ---- layer 2: aggregate F=64 (bufA -> bufC), GEMM 64->256 (-> bufA) ----
    k_agg64<<<(N_NODES * 32) / 256, 256>>>(rowptr, csrc, ccoef, bufA, dinv, bufC);
    {
        dim3 grid(256 / 64, N_NODES / 128);
        k_sgemm128<<<grid, 256>>>(bufC, W2, b2, bufA, 256, 64);
    }

    // ---- layer 3: aggregate F=256 (bufA -> bufB), GEMM 256->512 (-> bufC) ----
    k_agg256<<<(N_NODES * 32) / 256, 256>>>(rowptr, csrc, ccoef, bufA, dinv, bufB);
    {
        dim3 grid(512 / 64, N_NODES / 128);
        k_sgemm128<<<grid, 256>>>(bufB, W3, b3, bufC, 512, 256);
    }

    // ---- pooling + MLP head ----
    k_pool<<<N_GRAPHS, 512>>>(bufC, h);
    k_mlp1<<<N_GRAPHS, 512>>>(h, Wm1, bm1, h2);
    k_mlp2<<<(N_GRAPHS * 10 + 255) / 256, 256>>>(h2, Wm2, bm2, out);

    (void)in_sizes; (void)n_in; (void)out_size;
}